// round 9
// baseline (speedup 1.0000x reference)
#include <cuda_runtime.h>
#include <cuda_fp16.h>
#include <cstdint>
#include <cstddef>

// Problem constants
#define T_STEPS 512
#define BATCH   128
#define DIN     512
#define HID     512
#define G4      2048   // 4*HID

// ---------------------------------------------------------------------------
// Device-global scratch (allocation-free rule)
// ---------------------------------------------------------------------------
__device__ __half g_xh[(size_t)T_STEPS * BATCH * DIN];    // x as fp16
__device__ __half g_hbuf[2][(size_t)BATCH * HID];         // h as fp16, dbl-buf
__device__ unsigned int g_flag[4][T_STEPS][32];           // barrier flags
__device__ unsigned int g_exit;

// ---------------------------------------------------------------------------
// helpers
// ---------------------------------------------------------------------------
__device__ __forceinline__ void mma_f16(float* d,
    uint32_t a0, uint32_t a1, uint32_t a2, uint32_t a3,
    uint32_t b0, uint32_t b1)
{
    asm volatile(
        "mma.sync.aligned.m16n8k16.row.col.f32.f16.f16.f32 "
        "{%0,%1,%2,%3}, {%4,%5,%6,%7}, {%8,%9}, {%0,%1,%2,%3};\n"
        : "+f"(d[0]), "+f"(d[1]), "+f"(d[2]), "+f"(d[3])
        : "r"(a0), "r"(a1), "r"(a2), "r"(a3), "r"(b0), "r"(b1));
}

__device__ __forceinline__ void ldsm4(uint32_t* r, uint32_t addr) {
    asm volatile(
        "ldmatrix.sync.aligned.m8n8.x4.shared.b16 {%0,%1,%2,%3}, [%4];"
        : "=r"(r[0]), "=r"(r[1]), "=r"(r[2]), "=r"(r[3]) : "r"(addr));
}

__device__ __forceinline__ void cp16(uint32_t dst, const void* src) {
    asm volatile("cp.async.cg.shared.global [%0], [%1], 16;" :: "r"(dst), "l"(src));
}
__device__ __forceinline__ void cp_commit() {
    asm volatile("cp.async.commit_group;");
}
template <int N>
__device__ __forceinline__ void cp_wait() {
    asm volatile("cp.async.wait_group %0;" :: "n"(N));
}

__device__ __forceinline__ float fsigmoid(float x) {
    return __fdividef(1.0f, 1.0f + __expf(-x));
}
__device__ __forceinline__ float ftanh(float x) {
    float e = __expf(-2.0f * x);
    return __fdividef(2.0f, 1.0f + e) - 1.0f;
}

// ===========================================================================
// Prologue: fp32 -> fp16 conversion (x only)
// ===========================================================================
__global__ void cvt_f16_kernel(const float* __restrict__ src,
                               __half* __restrict__ dst, size_t n4)
{
    size_t i = (size_t)blockIdx.x * blockDim.x + threadIdx.x;
    size_t stride = (size_t)gridDim.x * blockDim.x;
    for (; i < n4; i += stride) {
        float4 v = ((const float4*)src)[i];
        __half2 lo = __floats2half2_rn(v.x, v.y);
        __half2 hi = __floats2half2_rn(v.z, v.w);
        uint2 u;
        u.x = *(uint32_t*)&lo;
        u.y = *(uint32_t*)&hi;
        ((uint2*)dst)[i] = u;
    }
}

// ===========================================================================
// Fused persistent LSTM kernel, 128 blocks x 256 threads (8 warps).
//   Block (bi,bj): 32 batch rows x 16 h-cols. Warp w: n-group (w&3) of 16
//   gate-interleaved cols, m-half (w>>2) of 16 rows -> 2 warps/SMSP for
//   latency overlap; k-loops are 2-stage software-pipelined (ldsm for s+1
//   issued before mma of s). Input-projection GEMM (x_{ts+1} @ Wx^T) fused
//   post-release; accumulators summed pre-shuffle.
// ===========================================================================
#define PB_PITCH 1040                               // 512 halves + 16B pad
#define WHS_OFF  0u
#define WXS_OFF  (64u * PB_PITCH)                   // 66560
#define HS_OFF   (WXS_OFF + 64u * PB_PITCH)         // 133120
#define XH_OFF   (HS_OFF + 32u * PB_PITCH)          // 166400
#define SMEM_B_BYTES (XH_OFF + 32u * PB_PITCH + 64) // 199744

__global__ __launch_bounds__(256, 1) void lstm_rec_kernel(
    const float* __restrict__ Wh,
    const float* __restrict__ Wx,
    const float* __restrict__ bxp,
    const float* __restrict__ bhp,
    float* __restrict__ out)
{
    extern __shared__ uint8_t smB[];
    const uint32_t sb = (uint32_t)__cvta_generic_to_shared(smB);

    const int tid  = threadIdx.x;
    const int warp = tid >> 5;
    const int lane = tid & 31;
    const int g    = lane >> 2;
    const int t    = lane & 3;
    const int odd  = t & 1;

    const int nq = warp & 3;        // n-group (4 h-cols x 4 gates = 16 B rows)
    const int mh = warp >> 2;       // m-half (16 rows)

    const int bi = blockIdx.x >> 5;
    const int bj = blockIdx.x & 31;
    const int b0 = bi * 32;
    const int j0 = bj * 16;

    // ---- one-time: Wh and Wx slices -> SMEM fp16, gate-interleaved rows ----
    for (int idx = tid; idx < 64 * 512; idx += 256) {
        int n = idx >> 9;
        int k = idx & 511;
        int w = n >> 4, p = n & 15;
        int grow = (p & 3) * HID + j0 + w * 4 + (p >> 2);
        *(__half*)(smB + WHS_OFF + (uint32_t)n * PB_PITCH + (uint32_t)k * 2) =
            __float2half_rn(Wh[(size_t)grow * HID + k]);
        *(__half*)(smB + WXS_OFF + (uint32_t)n * PB_PITCH + (uint32_t)k * 2) =
            __float2half_rn(Wx[(size_t)grow * DIN + k]);
    }

    // ---- bias registers for this thread's 2 h-cols ----
    float bias[2][4];
#pragma unroll
    for (int nt = 0; nt < 2; nt++) {
        int jc = j0 + nq * 4 + (t >> 1) + 2 * nt;
#pragma unroll
        for (int gate = 0; gate < 4; gate++)
            bias[nt][gate] = bxp[gate * HID + jc] + bhp[gate * HID + jc];
    }

    // ---- ldmatrix bases ----
    uint32_t rowsel = (uint32_t)((mh * 16 + (lane & 15)) * PB_PITCH + (lane >> 4) * 16);
    uint32_t aH = sb + HS_OFF + rowsel;
    uint32_t aX = sb + XH_OFF + rowsel;
    uint32_t brow = (uint32_t)((nq * 16 + (lane & 7) + ((lane >> 4) << 3)) * PB_PITCH
                               + ((lane >> 3) & 1) * 16);
    uint32_t aBh = sb + WHS_OFF + brow;
    uint32_t aBx = sb + WXS_OFF + brow;

    // x tile loader (8 chunks of 16B per thread = 32KB)
    auto issue_x = [&](int tsn) {
        const __half* src = g_xh + ((size_t)tsn * BATCH + b0) * DIN;
#pragma unroll
        for (int i = 0; i < 8; i++) {
            int id = i * 256 + tid;
            int r  = id >> 6;
            int u  = id & 63;
            cp16(sb + XH_OFF + (uint32_t)(r * PB_PITCH + u * 16),
                 src + (size_t)r * DIN + u * 8);
        }
        cp_commit();
    };

    float accx[2][4];
    float accr[2][4];
    float cst[2] = {0.f, 0.f};

    // 2-stage pipelined GEMM: A 16x512 @ B 16x512 -> acc[2][4]
    auto gemm16 = [&](uint32_t aA, uint32_t aB, float (*acc)[4]) {
        uint32_t a[2][4], b[2][4];
        ldsm4(a[0], aA);
        ldsm4(b[0], aB);
#pragma unroll 4
        for (int s = 0; s < 32; s++) {
            int cur = s & 1, nxt = cur ^ 1;
            if (s < 31) {
                uint32_t ko = (uint32_t)((s + 1) * 32);
                ldsm4(a[nxt], aA + ko);
                ldsm4(b[nxt], aB + ko);
            }
            mma_f16(acc[0], a[cur][0], a[cur][1], a[cur][2], a[cur][3],
                    b[cur][0], b[cur][1]);
            mma_f16(acc[1], a[cur][0], a[cur][1], a[cur][2], a[cur][3],
                    b[cur][2], b[cur][3]);
        }
    };

    // ---- prologue: x[0] -> Xh, xg-gemm for ts=0 ----
    issue_x(0);
    cp_wait<0>();
    __syncthreads();        // Whs/Wxs stores + Xh visible
#pragma unroll
    for (int nt = 0; nt < 2; nt++)
#pragma unroll
        for (int q = 0; q < 4; q++) accx[nt][q] = 0.0f;
    gemm16(aX, aBx, accx);

    for (int ts = 0; ts < T_STEPS; ts++) {
        if (ts > 0) {
            // ---- wait for peers to publish h_{ts-1} ----
            if (tid < 32) {
                const unsigned int* fp = &g_flag[bi][ts - 1][tid];
                unsigned v;
                do {
                    asm volatile("ld.acquire.gpu.global.u32 %0, [%1];"
                                 : "=r"(v) : "l"(fp) : "memory");
                } while (!v);
            }
            __syncthreads();   // also guards Xh reuse (all warps past xg gemm)

            // ---- h_{ts-1} tile -> Hs ----
            const __half* hsrc = g_hbuf[(ts - 1) & 1] + (size_t)b0 * HID;
#pragma unroll
            for (int i = 0; i < 8; i++) {
                int id = i * 256 + tid;
                int r  = id >> 6;
                int u  = id & 63;
                cp16(sb + HS_OFF + (uint32_t)(r * PB_PITCH + u * 16),
                     hsrc + (size_t)r * HID + u * 8);
            }
            cp_commit();
        }

        // ---- x[ts+1] tile -> Xh (separate, later commit group) ----
        if (ts + 1 < T_STEPS) issue_x(ts + 1);

        // ---- recurrent GEMM on top of accx ----
#pragma unroll
        for (int nt = 0; nt < 2; nt++)
#pragma unroll
            for (int q = 0; q < 4; q++) accr[nt][q] = accx[nt][q];

        if (ts > 0) {
            if (ts + 1 < T_STEPS) { cp_wait<1>(); } else { cp_wait<0>(); }
            __syncthreads();
            gemm16(aH, aBh, accr);
        }

        // ---- warp-local elementwise (gate shuffle), 2 elems/thread ----
        float hout[2];
#pragma unroll
        for (int nt = 0; nt < 2; nt++) {
            float q0 = accr[nt][0], q1 = accr[nt][1];
            float q2 = accr[nt][2], q3 = accr[nt][3];
            float sx = odd ? q0 : q2;
            float sy = odd ? q1 : q3;
            float rx = __shfl_xor_sync(0xffffffffu, sx, 1);
            float ry = __shfl_xor_sync(0xffffffffu, sy, 1);
            float gi = (odd ? rx : q0) + bias[nt][0];
            float gf = (odd ? ry : q1) + bias[nt][1];
            float gg = (odd ? q2 : rx) + bias[nt][2];
            float go = (odd ? q3 : ry) + bias[nt][3];

            float iv = fsigmoid(gi), fv = fsigmoid(gf);
            float gv = ftanh(gg),    ov = fsigmoid(go);
            float cn = cst[nt] * fv + iv * gv;
            cst[nt] = cn;
            float h = ov * ftanh(cn);
            hout[nt] = h;

            int rl = mh * 16 + g + (odd << 3);
            int jl = nq * 4 + (t >> 1) + 2 * nt;
            g_hbuf[ts & 1][(size_t)(b0 + rl) * HID + j0 + jl] = __float2half_rn(h);
        }

        __syncthreads();   // all hbuf stores issued before release

        if (ts < T_STEPS - 1) {
            if (tid == 0) {
                asm volatile("st.release.gpu.global.u32 [%0], %1;"
                             :: "l"(&g_flag[bi][ts][bj]), "r"(1u) : "memory");
            }
        }

        // ---- out fp32 stores (off the inter-block critical path) ----
        {
            float* obase = out + (size_t)ts * (BATCH * HID);
#pragma unroll
            for (int nt = 0; nt < 2; nt++) {
                int rl = mh * 16 + g + (odd << 3);
                int jl = nq * 4 + (t >> 1) + 2 * nt;
                obase[(size_t)(b0 + rl) * HID + j0 + jl] = hout[nt];
            }
        }

        // ---- input projection for ts+1 in the idle window ----
        if (ts + 1 < T_STEPS) {
            cp_wait<0>();      // x[ts+1] landed (own chunks)
            __syncthreads();   // everyone's chunks landed
#pragma unroll
            for (int nt = 0; nt < 2; nt++)
#pragma unroll
                for (int q = 0; q < 4; q++) accx[nt][q] = 0.0f;
            gemm16(aX, aBx, accx);
        }
    }

    // ---- exit: last block resets barrier state for next graph replay ----
    __syncthreads();
    volatile unsigned* rflag = (volatile unsigned*)(smB + XH_OFF);
    if (tid == 0) {
        unsigned old;
        asm volatile("atom.acq_rel.gpu.add.u32 %0, [%1], 1;"
                     : "=r"(old) : "l"(&g_exit) : "memory");
        *rflag = (old == 127u) ? 1u : 0u;
    }
    __syncthreads();
    if (*rflag != 0u) {
        unsigned int* fl = &g_flag[0][0][0];
        for (int i = tid; i < 4 * T_STEPS * 32; i += 256) fl[i] = 0u;
        __threadfence();
        if (tid == 0) g_exit = 0u;
    }
}

// ===========================================================================
// Launch
// ===========================================================================
extern "C" void kernel_launch(void* const* d_in, const int* in_sizes, int n_in,
                              void* d_out, int out_size)
{
    (void)in_sizes; (void)n_in; (void)out_size;
    const float* x  = (const float*)d_in[0];
    const float* Wx = (const float*)d_in[1];
    const float* bx = (const float*)d_in[2];
    const float* Wh = (const float*)d_in[3];
    const float* bh = (const float*)d_in[4];
    float* out = (float*)d_out;

    __half* xh;  cudaGetSymbolAddress((void**)&xh,  g_xh);

    cudaFuncSetAttribute(lstm_rec_kernel,
                         cudaFuncAttributeMaxDynamicSharedMemorySize, SMEM_B_BYTES);

    // x: fp32 -> fp16
    cvt_f16_kernel<<<2048, 256>>>(x, xh, (size_t)T_STEPS * BATCH * DIN / 4);

    // fused persistent LSTM
    lstm_rec_kernel<<<128, 256, SMEM_B_BYTES>>>(Wh, Wx, bx, bh, out);
}

// round 10
// speedup vs baseline: 1.1414x; 1.1414x over previous
#include <cuda_runtime.h>
#include <cuda_fp16.h>
#include <cstdint>
#include <cstddef>

// Problem constants
#define T_STEPS 512
#define BATCH   128
#define DIN     512
#define HID     512
#define G4      2048   // 4*HID

// ---------------------------------------------------------------------------
// Device-global scratch (allocation-free rule)
// ---------------------------------------------------------------------------
__device__ __half g_xh[(size_t)T_STEPS * BATCH * DIN];    // x as fp16
__device__ __half g_hbuf[2][(size_t)BATCH * HID];         // h as fp16, dbl-buf
__device__ unsigned int g_flag[4][T_STEPS][32];           // barrier flags
__device__ unsigned int g_exit;

// ---------------------------------------------------------------------------
// helpers
// ---------------------------------------------------------------------------
__device__ __forceinline__ void mma_f16(float* d,
    uint32_t a0, uint32_t a1, uint32_t a2, uint32_t a3,
    uint32_t b0, uint32_t b1)
{
    asm volatile(
        "mma.sync.aligned.m16n8k16.row.col.f32.f16.f16.f32 "
        "{%0,%1,%2,%3}, {%4,%5,%6,%7}, {%8,%9}, {%0,%1,%2,%3};\n"
        : "+f"(d[0]), "+f"(d[1]), "+f"(d[2]), "+f"(d[3])
        : "r"(a0), "r"(a1), "r"(a2), "r"(a3), "r"(b0), "r"(b1));
}

__device__ __forceinline__ void ldsm4(uint32_t* r, uint32_t addr) {
    asm volatile(
        "ldmatrix.sync.aligned.m8n8.x4.shared.b16 {%0,%1,%2,%3}, [%4];"
        : "=r"(r[0]), "=r"(r[1]), "=r"(r[2]), "=r"(r[3]) : "r"(addr));
}

__device__ __forceinline__ void cp16(uint32_t dst, const void* src) {
    asm volatile("cp.async.cg.shared.global [%0], [%1], 16;" :: "r"(dst), "l"(src));
}
__device__ __forceinline__ void cp_commit() {
    asm volatile("cp.async.commit_group;");
}
template <int N>
__device__ __forceinline__ void cp_wait() {
    asm volatile("cp.async.wait_group %0;" :: "n"(N));
}

#define BAR_SYNC(id, n) \
    asm volatile("bar.sync %0, %1;" :: "r"(id), "r"(n) : "memory")

__device__ __forceinline__ float fsigmoid(float x) {
    return __fdividef(1.0f, 1.0f + __expf(-x));
}
__device__ __forceinline__ float ftanh(float x) {
    float e = __expf(-2.0f * x);
    return __fdividef(2.0f, 1.0f + e) - 1.0f;
}

// ===========================================================================
// Prologue: fp32 -> fp16 conversion (x only)
// ===========================================================================
__global__ void cvt_f16_kernel(const float* __restrict__ src,
                               __half* __restrict__ dst, size_t n4)
{
    size_t i = (size_t)blockIdx.x * blockDim.x + threadIdx.x;
    size_t stride = (size_t)gridDim.x * blockDim.x;
    for (; i < n4; i += stride) {
        float4 v = ((const float4*)src)[i];
        __half2 lo = __floats2half2_rn(v.x, v.y);
        __half2 hi = __floats2half2_rn(v.z, v.w);
        uint2 u;
        u.x = *(uint32_t*)&lo;
        u.y = *(uint32_t*)&hi;
        ((uint2*)dst)[i] = u;
    }
}

// ===========================================================================
// Fused persistent LSTM, 128 blocks x 160 threads:
//   warps 0-3: compute (R8-proven mapping — warp w: 32 m-rows x 16 gate-
//              interleaved B rows = 4 h-cols), warp 4: loader.
//   Loader overlaps the flag-poll + h-tile cp.async with the compute warps'
//   fused input-projection GEMM; named barriers 1 (h ready) and 3 (x ready)
//   couple the two sides; barrier 2 is compute-only (pre-release ordering).
// ===========================================================================
#define PB_PITCH 1040                               // 512 halves + 16B pad
#define WHS_OFF  0u
#define WXS_OFF  (64u * PB_PITCH)                   // 66560
#define HS_OFF   (WXS_OFF + 64u * PB_PITCH)         // 133120
#define XH_OFF   (HS_OFF + 32u * PB_PITCH)          // 166400
#define SMEM_B_BYTES (XH_OFF + 32u * PB_PITCH + 64) // 199744

#define NTHREADS 160

__global__ __launch_bounds__(NTHREADS, 1) void lstm_rec_kernel(
    const float* __restrict__ Wh,
    const float* __restrict__ Wx,
    const float* __restrict__ bxp,
    const float* __restrict__ bhp,
    float* __restrict__ out)
{
    extern __shared__ uint8_t smB[];
    const uint32_t sb = (uint32_t)__cvta_generic_to_shared(smB);

    const int tid  = threadIdx.x;
    const int warp = tid >> 5;
    const int lane = tid & 31;
    const int g    = lane >> 2;
    const int t    = lane & 3;
    const int odd  = t & 1;

    const int bi = blockIdx.x >> 5;
    const int bj = blockIdx.x & 31;
    const int b0 = bi * 32;
    const int j0 = bj * 16;

    const bool is_loader = (warp == 4);

    // ---- one-time: Wh and Wx slices -> SMEM fp16, gate-interleaved rows ----
    for (int idx = tid; idx < 64 * 512; idx += NTHREADS) {
        int n = idx >> 9;
        int k = idx & 511;
        int w = n >> 4, p = n & 15;
        int grow = (p & 3) * HID + j0 + w * 4 + (p >> 2);
        *(__half*)(smB + WHS_OFF + (uint32_t)n * PB_PITCH + (uint32_t)k * 2) =
            __float2half_rn(Wh[(size_t)grow * HID + k]);
        *(__half*)(smB + WXS_OFF + (uint32_t)n * PB_PITCH + (uint32_t)k * 2) =
            __float2half_rn(Wx[(size_t)grow * DIN + k]);
    }

    // ---- bias registers (compute warps only) ----
    float bias[2][4];
    if (!is_loader) {
#pragma unroll
        for (int nt = 0; nt < 2; nt++) {
            int jc = j0 + warp * 4 + (t >> 1) + 2 * nt;
#pragma unroll
            for (int gate = 0; gate < 4; gate++)
                bias[nt][gate] = bxp[gate * HID + jc] + bhp[gate * HID + jc];
        }
    }

    // ---- ldmatrix bases (compute warps; R8 mapping) ----
    uint32_t rowsel = (uint32_t)((lane & 15) * PB_PITCH + (lane >> 4) * 16);
    uint32_t aH0 = sb + HS_OFF + rowsel;
    uint32_t aH1 = sb + HS_OFF + (uint32_t)(16 * PB_PITCH) + rowsel;
    uint32_t aX0 = sb + XH_OFF + rowsel;
    uint32_t aX1 = sb + XH_OFF + (uint32_t)(16 * PB_PITCH) + rowsel;
    uint32_t brow = (uint32_t)(((warp & 3) * 16 + (lane & 7) + ((lane >> 4) << 3)) * PB_PITCH
                               + ((lane >> 3) & 1) * 16);
    uint32_t aBh = sb + WHS_OFF + brow;
    uint32_t aBx = sb + WXS_OFF + brow;

    // ---- loader lambdas (warp 4 only; 64 chunks of 16B per lane) ----
    auto load_x = [&](int tsn) {
        const __half* src = g_xh + ((size_t)tsn * BATCH + b0) * DIN;
#pragma unroll
        for (int i = 0; i < 64; i++) {
            int id = i * 32 + lane;
            int r  = id >> 6;
            int u  = id & 63;
            cp16(sb + XH_OFF + (uint32_t)(r * PB_PITCH + u * 16),
                 src + (size_t)r * DIN + u * 8);
        }
        cp_commit();
    };
    auto load_h = [&](int tsp) {
        const __half* src = g_hbuf[tsp & 1] + (size_t)b0 * HID;
#pragma unroll
        for (int i = 0; i < 64; i++) {
            int id = i * 32 + lane;
            int r  = id >> 6;
            int u  = id & 63;
            cp16(sb + HS_OFF + (uint32_t)(r * PB_PITCH + u * 16),
                 src + (size_t)r * HID + u * 8);
        }
        cp_commit();
    };

    float accx[2][2][4];
    float accr[2][2][4];
    float cst[2][2] = {{0.f, 0.f}, {0.f, 0.f}};

    auto xg_gemm = [&]() {
#pragma unroll
        for (int mt = 0; mt < 2; mt++)
#pragma unroll
            for (int nt = 0; nt < 2; nt++)
#pragma unroll
                for (int q = 0; q < 4; q++) accx[mt][nt][q] = 0.0f;
#pragma unroll 4
        for (int s = 0; s < 32; s++) {
            uint32_t ko = (uint32_t)(s * 32);
            uint32_t a0[4], a1[4], bb[4];
            ldsm4(a0, aX0 + ko);
            ldsm4(a1, aX1 + ko);
            ldsm4(bb, aBx + ko);
            mma_f16(accx[0][0], a0[0], a0[1], a0[2], a0[3], bb[0], bb[1]);
            mma_f16(accx[0][1], a0[0], a0[1], a0[2], a0[3], bb[2], bb[3]);
            mma_f16(accx[1][0], a1[0], a1[1], a1[2], a1[3], bb[0], bb[1]);
            mma_f16(accx[1][1], a1[0], a1[1], a1[2], a1[3], bb[2], bb[3]);
        }
    };

    // ---- prologue: x[0] -> Xh (loader), xg-gemm for ts=0 (compute) ----
    if (is_loader) { load_x(0); cp_wait<0>(); }
    __syncthreads();        // weights + x[0] visible to all
    if (!is_loader) xg_gemm();

    for (int ts = 0; ts < T_STEPS; ts++) {
        if (is_loader) {
            if (ts > 0) {
                // poll flags (one per lane), then pull h_{ts-1}
                const unsigned int* fp = &g_flag[bi][ts - 1][lane];
                unsigned v;
                do {
                    asm volatile("ld.acquire.gpu.global.u32 %0, [%1];"
                                 : "=r"(v) : "l"(fp) : "memory");
                } while (!v);
                __syncwarp();
                load_h(ts - 1);
                cp_wait<0>();
            }
            BAR_SYNC(1, NTHREADS);             // barA: h ready / Xh consumed
            if (ts + 1 < T_STEPS) {
                load_x(ts + 1);
                cp_wait<0>();
                BAR_SYNC(3, NTHREADS);         // barB: x[ts+1] ready
            }
        } else {
            // ---- compute ----
#pragma unroll
            for (int mt = 0; mt < 2; mt++)
#pragma unroll
                for (int nt = 0; nt < 2; nt++)
#pragma unroll
                    for (int q = 0; q < 4; q++) accr[mt][nt][q] = accx[mt][nt][q];

            BAR_SYNC(1, NTHREADS);             // barA

            if (ts > 0) {
                // recurrent GEMM: Hs @ Whs (accumulate into accr)
#pragma unroll 4
                for (int s = 0; s < 32; s++) {
                    uint32_t ko = (uint32_t)(s * 32);
                    uint32_t a0[4], a1[4], bb[4];
                    ldsm4(a0, aH0 + ko);
                    ldsm4(a1, aH1 + ko);
                    ldsm4(bb, aBh + ko);
                    mma_f16(accr[0][0], a0[0], a0[1], a0[2], a0[3], bb[0], bb[1]);
                    mma_f16(accr[0][1], a0[0], a0[1], a0[2], a0[3], bb[2], bb[3]);
                    mma_f16(accr[1][0], a1[0], a1[1], a1[2], a1[3], bb[0], bb[1]);
                    mma_f16(accr[1][1], a1[0], a1[1], a1[2], a1[3], bb[2], bb[3]);
                }
            }

            // ---- warp-local elementwise (gate shuffle), 4 elems/thread ----
            float hout[2][2];
#pragma unroll
            for (int mt = 0; mt < 2; mt++) {
#pragma unroll
                for (int nt = 0; nt < 2; nt++) {
                    float q0 = accr[mt][nt][0], q1 = accr[mt][nt][1];
                    float q2 = accr[mt][nt][2], q3 = accr[mt][nt][3];
                    float sx = odd ? q0 : q2;
                    float sy = odd ? q1 : q3;
                    float rx = __shfl_xor_sync(0xffffffffu, sx, 1);
                    float ry = __shfl_xor_sync(0xffffffffu, sy, 1);
                    float gi = (odd ? rx : q0) + bias[nt][0];
                    float gf = (odd ? ry : q1) + bias[nt][1];
                    float gg = (odd ? q2 : rx) + bias[nt][2];
                    float go = (odd ? q3 : ry) + bias[nt][3];

                    float iv = fsigmoid(gi), fv = fsigmoid(gf);
                    float gv = ftanh(gg),    ov = fsigmoid(go);
                    float cn = cst[mt][nt] * fv + iv * gv;
                    cst[mt][nt] = cn;
                    float h = ov * ftanh(cn);
                    hout[mt][nt] = h;

                    int rl = mt * 16 + g + (odd << 3);
                    int jl = (warp & 3) * 4 + (t >> 1) + 2 * nt;
                    g_hbuf[ts & 1][(size_t)(b0 + rl) * HID + j0 + jl] =
                        __float2half_rn(h);
                }
            }

            BAR_SYNC(2, 128);                  // compute-only: stores ordered

            if (ts < T_STEPS - 1 && tid == 0) {
                asm volatile("st.release.gpu.global.u32 [%0], %1;"
                             :: "l"(&g_flag[bi][ts][bj]), "r"(1u) : "memory");
            }

            // out fp32 stores (off the inter-block critical path)
            {
                float* obase = out + (size_t)ts * (BATCH * HID);
#pragma unroll
                for (int mt = 0; mt < 2; mt++)
#pragma unroll
                    for (int nt = 0; nt < 2; nt++) {
                        int rl = mt * 16 + g + (odd << 3);
                        int jl = (warp & 3) * 4 + (t >> 1) + 2 * nt;
                        obase[(size_t)(b0 + rl) * HID + j0 + jl] = hout[mt][nt];
                    }
            }

            if (ts + 1 < T_STEPS) {
                BAR_SYNC(3, NTHREADS);         // barB: x[ts+1] in Xh
                xg_gemm();                     // runs while loader polls/loads h
            }
        }
    }

    // ---- exit: last block resets barrier state for next graph replay ----
    __syncthreads();
    volatile unsigned* rflag = (volatile unsigned*)(smB + XH_OFF);
    if (tid == 0) {
        unsigned old;
        asm volatile("atom.acq_rel.gpu.add.u32 %0, [%1], 1;"
                     : "=r"(old) : "l"(&g_exit) : "memory");
        *rflag = (old == 127u) ? 1u : 0u;
    }
    __syncthreads();
    if (*rflag != 0u) {
        unsigned int* fl = &g_flag[0][0][0];
        for (int i = tid; i < 4 * T_STEPS * 32; i += NTHREADS) fl[i] = 0u;
        __threadfence();
        if (tid == 0) g_exit = 0u;
    }
}

// ===========================================================================
// Launch
// ===========================================================================
extern "C" void kernel_launch(void* const* d_in, const int* in_sizes, int n_in,
                              void* d_out, int out_size)
{
    (void)in_sizes; (void)n_in; (void)out_size;
    const float* x  = (const float*)d_in[0];
    const float* Wx = (const float*)d_in[1];
    const float* bx = (const float*)d_in[2];
    const float* Wh = (const float*)d_in[3];
    const float* bh = (const float*)d_in[4];
    float* out = (float*)d_out;

    __half* xh;  cudaGetSymbolAddress((void**)&xh,  g_xh);

    cudaFuncSetAttribute(lstm_rec_kernel,
                         cudaFuncAttributeMaxDynamicSharedMemorySize, SMEM_B_BYTES);

    // x: fp32 -> fp16
    cvt_f16_kernel<<<2048, 256>>>(x, xh, (size_t)T_STEPS * BATCH * DIN / 4);

    // fused persistent LSTM
    lstm_rec_kernel<<<128, NTHREADS, SMEM_B_BYTES>>>(Wh, Wx, bx, bh, out);
}